// round 5
// baseline (speedup 1.0000x reference)
#include <cuda_runtime.h>
#include <cstdint>

#define B 16
#define P 512          // m = n = 512
#define D 128
#define ITERS 20

// ---------------- device scratch (allocation-free rule: __device__ globals) --
__device__ float g_qm[(size_t)B * P * P];   // 16 MB, (b, j, i) row-major, i contiguous
__device__ float g_ra[B * P];               // ||u_i||^2 (cur)
__device__ float g_rb[B * P];               // ||v_j||^2 (nxt)
__device__ float g_qsq[B];                  // sum qm^2 per batch (for lr)
__device__ float g_qsum[B];                 // sum qm per batch (for s0)
// double-buffered per-rank partials: [buf][b][rank][ T[512] | C[512] ]
__device__ float g_part[2 * B * 8 * 1024];
__device__ unsigned g_qpbar[B];             // per-batch arrival counter

// ---------------- helpers ----------------------------------------------------
__device__ __forceinline__ float wred(float v) {
    v += __shfl_xor_sync(0xffffffffu, v, 16);
    v += __shfl_xor_sync(0xffffffffu, v, 8);
    v += __shfl_xor_sync(0xffffffffu, v, 4);
    v += __shfl_xor_sync(0xffffffffu, v, 2);
    v += __shfl_xor_sync(0xffffffffu, v, 1);
    return v;
}

// packed f32x2 fma: d.lo += a.lo*b.lo ; d.hi += a.hi*b.hi (2 MACs / issue slot)
__device__ __forceinline__ void ffma2(unsigned long long& d,
                                      unsigned long long a, unsigned long long b) {
    asm("fma.rn.f32x2 %0, %1, %2, %0;" : "+l"(d) : "l"(a), "l"(b));
}

__device__ __forceinline__ float f32x2_hsum(unsigned long long v) {
    float lo, hi;
    asm("mov.b64 {%0, %1}, %2;" : "=f"(lo), "=f"(hi) : "l"(v));
    return lo + hi;
}

// ---------------- kernel 1: row norms + scalar zeroing ------------------------
__global__ void norms_kernel(const float* __restrict__ ncur, const float* __restrict__ ecur,
                             const float* __restrict__ nnxt, const float* __restrict__ enxt) {
    int gw = blockIdx.x * (blockDim.x >> 5) + (threadIdx.x >> 5);   // row id in [0, 8192)
    int l  = threadIdx.x & 31;
    size_t base = (size_t)gw * D;

    float4 a1 = ((const float4*)(ncur + base))[l];
    float4 a2 = ((const float4*)(ecur + base))[l];
    float4 b1 = ((const float4*)(nnxt + base))[l];
    float4 b2 = ((const float4*)(enxt + base))[l];

    float sa = a1.x*a1.x + a1.y*a1.y + a1.z*a1.z + a1.w*a1.w
             + a2.x*a2.x + a2.y*a2.y + a2.z*a2.z + a2.w*a2.w;
    float sb = b1.x*b1.x + b1.y*b1.y + b1.z*b1.z + b1.w*b1.w
             + b2.x*b2.x + b2.y*b2.y + b2.z*b2.z + b2.w*b2.w;
    sa = wred(sa);
    sb = wred(sb);
    if (l == 0) { g_ra[gw] = sa; g_rb[gw] = sb; }
    if (blockIdx.x == 0 && threadIdx.x < B) {
        g_qsq[threadIdx.x] = 0.f; g_qsum[threadIdx.x] = 0.f; g_qpbar[threadIdx.x] = 0u;
    }
}

// ---------------- kernel 2: gram / cost matrix (packed f32x2 math) ------------
// qm[b, j, i] = 0.5*(ra_i + rb_j) - (ncur_i.nnxt_j + ecur_i.enxt_j)
// SMEM holds k-PAIR interleaved tiles: Us[k2][i][2] = (val at 2*k2, val at 2*k2+1)
// so a single LDS.128 yields two ready-packed 64-bit f32x2 operands.
#define K2W 132   // floats per k2-row: 64 cols * 2 + 4 pad (keeps 16B alignment)

__global__ __launch_bounds__(256) void gram_kernel(
    const float* __restrict__ ncur, const float* __restrict__ ecur,
    const float* __restrict__ nnxt, const float* __restrict__ enxt) {

    __shared__ __align__(16) float Us[32 * K2W];
    __shared__ __align__(16) float Vs[32 * K2W];
    __shared__ float sQred[8];
    __shared__ float sSred[8];

    const int b  = blockIdx.z;
    const int i0 = blockIdx.x * 64;
    const int j0 = blockIdx.y * 64;
    const int tid = threadIdx.x;
    const int tx = tid & 15;       // i micro (4 cols)
    const int ty = tid >> 4;       // j micro (4 rows)

    unsigned long long acc2[4][4]; // [r][c], lanes = (even-k partial, odd-k partial)
    #pragma unroll
    for (int r = 0; r < 4; r++)
        #pragma unroll
        for (int c = 0; c < 4; c++) acc2[r][c] = 0ull;

    const int row = tid >> 2;      // 0..63 (loader row)
    const int kq  = tid & 3;

    for (int kc = 0; kc < 4; kc++) {
        const float* usrc = ((kc & 2) ? ecur : ncur) + (size_t)b * (P * D);
        const float* vsrc = ((kc & 2) ? enxt : nnxt) + (size_t)b * (P * D);

        // thread loads k = q*16 + kq*4 + {0..3} within this 64-wide chunk
        const float4* up = (const float4*)(usrc + (size_t)(i0 + row) * D) + (kc & 1) * 16;
        const float4* vp = (const float4*)(vsrc + (size_t)(j0 + row) * D) + (kc & 1) * 16;
        float4 ur[4], vr[4];
        #pragma unroll
        for (int q = 0; q < 4; q++) { ur[q] = up[q * 4 + kq]; vr[q] = vp[q * 4 + kq]; }

        __syncthreads();   // previous chunk's compute done
        #pragma unroll
        for (int q = 0; q < 4; q++) {
            const int k2 = q * 8 + kq * 2;     // pair row for k = q*16+kq*4
            *(float2*)&Us[(k2)     * K2W + row * 2] = make_float2(ur[q].x, ur[q].y);
            *(float2*)&Us[(k2 + 1) * K2W + row * 2] = make_float2(ur[q].z, ur[q].w);
            *(float2*)&Vs[(k2)     * K2W + row * 2] = make_float2(vr[q].x, vr[q].y);
            *(float2*)&Vs[(k2 + 1) * K2W + row * 2] = make_float2(vr[q].z, vr[q].w);
        }
        __syncthreads();

        #pragma unroll 8
        for (int k2 = 0; k2 < 32; k2++) {
            const ulonglong2* ub = (const ulonglong2*)&Us[k2 * K2W + tx * 8];
            const ulonglong2* vb = (const ulonglong2*)&Vs[k2 * K2W + ty * 8];
            ulonglong2 ua = ub[0], uc = ub[1];
            ulonglong2 va = vb[0], vc = vb[1];
            unsigned long long up2[4] = {ua.x, ua.y, uc.x, uc.y};
            unsigned long long vp2[4] = {va.x, va.y, vc.x, vc.y};
            #pragma unroll
            for (int r = 0; r < 4; r++)
                #pragma unroll
                for (int c = 0; c < 4; c++)
                    ffma2(acc2[r][c], up2[c], vp2[r]);
        }
    }

    // horizontal sum of the two k-parity lanes
    float acc[4][4];
    #pragma unroll
    for (int r = 0; r < 4; r++)
        #pragma unroll
        for (int c = 0; c < 4; c++) acc[r][c] = f32x2_hsum(acc2[r][c]);

    float raL[4], rbL[4];
    #pragma unroll
    for (int c = 0; c < 4; c++) raL[c] = g_ra[b * P + i0 + tx * 4 + c];
    #pragma unroll
    for (int r = 0; r < 4; r++) rbL[r] = g_rb[b * P + j0 + ty * 4 + r];

    float qs = 0.f, q1 = 0.f;
    #pragma unroll
    for (int r = 0; r < 4; r++) {
        float4 o;
        o.x = 0.5f * (raL[0] + rbL[r]) - acc[r][0];
        o.y = 0.5f * (raL[1] + rbL[r]) - acc[r][1];
        o.z = 0.5f * (raL[2] + rbL[r]) - acc[r][2];
        o.w = 0.5f * (raL[3] + rbL[r]) - acc[r][3];
        qs += o.x*o.x + o.y*o.y + o.z*o.z + o.w*o.w;
        q1 += o.x + o.y + o.z + o.w;
        *(float4*)&g_qm[((size_t)b * P + j0 + ty * 4 + r) * P + i0 + tx * 4] = o;
    }
    qs = wred(qs);
    q1 = wred(q1);
    if ((tid & 31) == 0) { sQred[tid >> 5] = qs; sSred[tid >> 5] = q1; }
    __syncthreads();
    if (tid == 0) {
        float t = 0.f, t2 = 0.f;
        #pragma unroll
        for (int w = 0; w < 8; w++) { t += sQred[w]; t2 += sSred[w]; }
        atomicAdd(&g_qsq[b], t);
        atomicAdd(&g_qsum[b], t2);
    }
}

// ---------------- kernel 3: persistent QP solve, NO clusters -------------------
// 128 plain CTAs (8 per batch), each owns 64 rows of X in SMEM. Cross-CTA data
// goes through L2 (.cg) with a release/acquire counter barrier; every CTA
// redundantly computes all 512 column scales + scalar s — one barrier/iter.
#define SM_X      0                      // 32768 floats
#define SM_TW     32768                  // 16*512 per-warp T partials
#define SM_CW     (SM_TW + 8192)         // 16*512 per-warp colsum partials
#define SM_SCALE  (SM_CW + 8192)         // 512 (col scale, lazy)
#define SM_RED    (SM_SCALE + 512)       // 16
#define SM_S      (SM_RED + 16)          // 4
#define QP_SMEM_FLOATS (SM_S + 4)
#define QP_SMEM_BYTES  (QP_SMEM_FLOATS * 4)

__global__ void __launch_bounds__(512, 1)
qp_kernel(float* __restrict__ out) {
    extern __shared__ float sm[];
    float4* sX4    = (float4*)(sm + SM_X);
    float4* sTw4   = (float4*)(sm + SM_TW);
    float4* sCw4   = (float4*)(sm + SM_CW);
    float*  sScale = sm + SM_SCALE;
    float4* sSc4   = (float4*)sScale;
    float*  sRed   = sm + SM_RED;
    float*  sS     = sm + SM_S;

    const int b    = blockIdx.x >> 3;
    const int rank = blockIdx.x & 7;
    const int tid  = threadIdx.x;
    const int w    = tid >> 5, l = tid & 31;

    const float lr = 0.5f / (g_qsq[b] + 1e-8f);
    float s = g_qsum[b] * (1.f / 512.f);     // s0: X = 1/512, scale = 1
    const float4* qm4 = (const float4*)(g_qm + ((size_t)b * P + rank * 64) * P);

    // init: X = 1/512, scale = 1
    const float4 iv = make_float4(1.f/512, 1.f/512, 1.f/512, 1.f/512);
    for (int idx = tid; idx < 8192; idx += 512) sX4[idx] = iv;
    if (tid < 128) sSc4[tid] = make_float4(1.f, 1.f, 1.f, 1.f);
    __syncthreads();

    for (int it = 0; it < ITERS; it++) {
        const float cq = 2.f * lr * s;

        // ---- phase A: gradient + clip + row-normalize + per-column T/C partials
        float4 tA[4] = {}, cA[4] = {};
        #pragma unroll
        for (int q = 0; q < 4; q++) {
            const int jl = w * 4 + q;
            const float4* qrow = qm4 + jl * 128;
            float4* xrow = sX4 + jl * 128;
            float4 qv[4], vv[4];
            float rs = 0.f;
            #pragma unroll
            for (int t = 0; t < 4; t++) {
                const int c4 = l + 32 * t;
                qv[t] = qrow[c4];                     // L2 (single read per iter)
                float4 x  = xrow[c4];
                float4 sc = sSc4[c4];
                float4 v;
                v.x = fminf(fmaxf(fmaf(-cq, qv[t].x, x.x * sc.x), 0.f), 1.f);
                v.y = fminf(fmaxf(fmaf(-cq, qv[t].y, x.y * sc.y), 0.f), 1.f);
                v.z = fminf(fmaxf(fmaf(-cq, qv[t].z, x.z * sc.z), 0.f), 1.f);
                v.w = fminf(fmaxf(fmaf(-cq, qv[t].w, x.w * sc.w), 0.f), 1.f);
                vv[t] = v;
                rs += v.x + v.y + v.z + v.w;
            }
            rs = wred(rs);
            const float inv = 1.f / (rs + 1e-8f);
            #pragma unroll
            for (int t = 0; t < 4; t++) {
                const int c4 = l + 32 * t;
                float4 v = vv[t];
                v.x *= inv; v.y *= inv; v.z *= inv; v.w *= inv;
                xrow[c4] = v;                         // Xnorm back to SMEM
                tA[t].x += qv[t].x * v.x; tA[t].y += qv[t].y * v.y;
                tA[t].z += qv[t].z * v.z; tA[t].w += qv[t].w * v.w;
                cA[t].x += v.x; cA[t].y += v.y; cA[t].z += v.z; cA[t].w += v.w;
            }
        }
        #pragma unroll
        for (int t = 0; t < 4; t++) {
            const int c4 = l + 32 * t;
            sTw4[w * 128 + c4] = tA[t];
            sCw4[w * 128 + c4] = cA[t];
        }
        __syncthreads();

        // ---- CTA-level column totals -> global partial slot (L2, .cg)
        const int buf = it & 1;
        float* gslot = g_part + ((size_t)buf * B + b) * 8192 + rank * 1024;
        if (tid < 256) {
            const int arr = tid >> 7;         // 0 -> T, 1 -> C
            const int c4  = tid & 127;
            const float4* src = (arr ? sCw4 : sTw4) + c4;
            float4 a = make_float4(0.f, 0.f, 0.f, 0.f);
            #pragma unroll
            for (int ww = 0; ww < 16; ww++) {
                float4 vv = src[ww * 128];
                a.x += vv.x; a.y += vv.y; a.z += vv.z; a.w += vv.w;
            }
            __stcg((float4*)(gslot + arr * 512) + c4, a);
        }
        __syncthreads();

        // ---- single global barrier per batch (release arrive, acquire spin)
        // red.release orders the prior .cg stores; no separate fence needed.
        if (tid == 0) {
            asm volatile("red.release.gpu.global.add.u32 [%0], %1;"
                         :: "l"(&g_qpbar[b]), "r"(1u) : "memory");
            const unsigned target = 8u * (unsigned)(it + 1);
            unsigned v;
            do {
                asm volatile("ld.acquire.gpu.global.u32 %0, [%1];"
                             : "=r"(v) : "l"(&g_qpbar[b]) : "memory");
                if (v >= target) break;
                __nanosleep(32);
            } while (true);
        }
        __syncthreads();

        // ---- phase B (redundant per CTA): col scale for ALL 512 cols + scalar s
        {
            const float* pb = g_part + ((size_t)buf * B + b) * 8192;
            float Tt = 0.f, Ct = 0.f;
            #pragma unroll
            for (int r = 0; r < 8; r++) {
                Tt += __ldcg(pb + r * 1024 + tid);
                Ct += __ldcg(pb + r * 1024 + 512 + tid);
            }
            const float scl = fminf(1.f, 2.f / (Ct + 1e-8f));
            sScale[tid] = scl;
            float contrib = wred(scl * Tt);
            if (l == 0) sRed[w] = contrib;
        }
        __syncthreads();
        if (tid < 32) {
            float v = (tid < 16) ? sRed[tid] : 0.f;
            v = wred(v);
            if (tid == 0) sS[0] = v;
        }
        __syncthreads();
        s = sS[0];
    }

    // ---- writeout: apply final lazy col scale
    float4* out4 = (float4*)out + ((size_t)b * P + rank * 64) * 128;
    for (int idx = tid; idx < 8192; idx += 512) {
        float4 x = sX4[idx], sc = sSc4[idx & 127];
        out4[idx] = make_float4(x.x * sc.x, x.y * sc.y, x.z * sc.z, x.w * sc.w);
    }
}

// ---------------- launch -------------------------------------------------------
extern "C" void kernel_launch(void* const* d_in, const int* in_sizes, int n_in,
                              void* d_out, int out_size) {
    (void)in_sizes; (void)n_in; (void)out_size;
    const float* ncur = (const float*)d_in[0];
    const float* ecur = (const float*)d_in[1];
    const float* nnxt = (const float*)d_in[2];
    const float* enxt = (const float*)d_in[3];
    float* out = (float*)d_out;

    cudaFuncSetAttribute(qp_kernel, cudaFuncAttributeMaxDynamicSharedMemorySize, QP_SMEM_BYTES);

    norms_kernel<<<1024, 256>>>(ncur, ecur, nnxt, enxt);
    gram_kernel<<<dim3(8, 8, B), 256>>>(ncur, ecur, nnxt, enxt);
    qp_kernel<<<128, 512, QP_SMEM_BYTES>>>(out);
}

// round 7
// speedup vs baseline: 1.0449x; 1.0449x over previous
#include <cuda_runtime.h>
#include <cstdint>

#define B 16
#define P 512          // m = n = 512
#define D 128
#define ITERS 20

typedef unsigned long long ull;

// ---------------- device scratch (allocation-free rule: __device__ globals) --
__device__ float g_qm[(size_t)B * P * P];   // 16 MB, (b, j, i) row-major, i contiguous
__device__ float g_ra[B * P];               // ||u_i||^2 (cur)
__device__ float g_rb[B * P];               // ||v_j||^2 (nxt)
__device__ float g_qsq[B];                  // sum qm^2 per batch (for lr)
__device__ float g_qsum[B];                 // sum qm per batch (for s0)
// double-buffered per-rank partials: [buf][b][rank][ T[512] | C[512] ]
__device__ float g_part[2 * B * 8 * 1024];
__device__ unsigned g_qpbar[B];             // per-batch arrival counter

// ---------------- helpers ----------------------------------------------------
__device__ __forceinline__ float wred(float v) {
    v += __shfl_xor_sync(0xffffffffu, v, 16);
    v += __shfl_xor_sync(0xffffffffu, v, 8);
    v += __shfl_xor_sync(0xffffffffu, v, 4);
    v += __shfl_xor_sync(0xffffffffu, v, 2);
    v += __shfl_xor_sync(0xffffffffu, v, 1);
    return v;
}

// ---- packed f32x2 ops (sm_100+ packed fp32: add/mul/fma only) ---------------
__device__ __forceinline__ ull pk2(float lo, float hi) {
    ull r; asm("mov.b64 %0, {%1, %2};" : "=l"(r) : "f"(lo), "f"(hi)); return r;
}
__device__ __forceinline__ ull mul2(ull a, ull b) {
    ull d; asm("mul.rn.f32x2 %0, %1, %2;" : "=l"(d) : "l"(a), "l"(b)); return d;
}
__device__ __forceinline__ ull add2(ull a, ull b) {
    ull d; asm("add.rn.f32x2 %0, %1, %2;" : "=l"(d) : "l"(a), "l"(b)); return d;
}
__device__ __forceinline__ ull fma2(ull a, ull b, ull c) {
    ull d; asm("fma.rn.f32x2 %0, %1, %2, %3;" : "=l"(d) : "l"(a), "l"(b), "l"(c)); return d;
}
__device__ __forceinline__ float hsum2(ull v) {
    float lo, hi; asm("mov.b64 {%0, %1}, %2;" : "=f"(lo), "=f"(hi) : "l"(v));
    return lo + hi;
}
// clamp both lanes to [0,1]: unpack is register-pair aliasing (near-free),
// 4 FMNMX, repack. No packed min/max exists in ptxas.
__device__ __forceinline__ ull clamp01_2(ull v) {
    float lo, hi; asm("mov.b64 {%0, %1}, %2;" : "=f"(lo), "=f"(hi) : "l"(v));
    lo = fminf(fmaxf(lo, 0.f), 1.f);
    hi = fminf(fmaxf(hi, 0.f), 1.f);
    ull r; asm("mov.b64 %0, {%1, %2};" : "=l"(r) : "f"(lo), "f"(hi)); return r;
}

// ---------------- kernel 1: row norms + scalar zeroing ------------------------
__global__ void norms_kernel(const float* __restrict__ ncur, const float* __restrict__ ecur,
                             const float* __restrict__ nnxt, const float* __restrict__ enxt) {
    int gw = blockIdx.x * (blockDim.x >> 5) + (threadIdx.x >> 5);   // row id in [0, 8192)
    int l  = threadIdx.x & 31;
    size_t base = (size_t)gw * D;

    float4 a1 = ((const float4*)(ncur + base))[l];
    float4 a2 = ((const float4*)(ecur + base))[l];
    float4 b1 = ((const float4*)(nnxt + base))[l];
    float4 b2 = ((const float4*)(enxt + base))[l];

    float sa = a1.x*a1.x + a1.y*a1.y + a1.z*a1.z + a1.w*a1.w
             + a2.x*a2.x + a2.y*a2.y + a2.z*a2.z + a2.w*a2.w;
    float sb = b1.x*b1.x + b1.y*b1.y + b1.z*b1.z + b1.w*b1.w
             + b2.x*b2.x + b2.y*b2.y + b2.z*b2.z + b2.w*b2.w;
    sa = wred(sa);
    sb = wred(sb);
    if (l == 0) { g_ra[gw] = sa; g_rb[gw] = sb; }
    if (blockIdx.x == 0 && threadIdx.x < B) {
        g_qsq[threadIdx.x] = 0.f; g_qsum[threadIdx.x] = 0.f; g_qpbar[threadIdx.x] = 0u;
    }
}

// ---------------- kernel 2: gram / cost matrix (R4 proven version) -----------
// qm[b, j, i] = 0.5*(ra_i + rb_j) - (ncur_i.nnxt_j + ecur_i.enxt_j)
__global__ __launch_bounds__(256) void gram_kernel(
    const float* __restrict__ ncur, const float* __restrict__ ecur,
    const float* __restrict__ nnxt, const float* __restrict__ enxt) {

    __shared__ float Us[64][68];
    __shared__ float Vs[64][68];
    __shared__ float sQred[8];
    __shared__ float sSred[8];

    const int b  = blockIdx.z;
    const int i0 = blockIdx.x * 64;
    const int j0 = blockIdx.y * 64;
    const int tid = threadIdx.x;
    const int tx = tid & 15;
    const int ty = tid >> 4;

    float acc[4][4] = {};

    const int row = tid >> 2;
    const int kq  = tid & 3;

    for (int kc = 0; kc < 4; kc++) {
        const float* usrc = ((kc & 2) ? ecur : ncur) + (size_t)b * (P * D) + (kc & 1) * 64;
        const float* vsrc = ((kc & 2) ? enxt : nnxt) + (size_t)b * (P * D) + (kc & 1) * 64;

        const float4* up = (const float4*)(usrc + (size_t)(i0 + row) * D) + kq * 4;
        const float4* vp = (const float4*)(vsrc + (size_t)(j0 + row) * D) + kq * 4;
        float4 ur[4], vr[4];
        #pragma unroll
        for (int q = 0; q < 4; q++) { ur[q] = up[q]; vr[q] = vp[q]; }

        __syncthreads();
        #pragma unroll
        for (int q = 0; q < 4; q++) {
            int kk = kq * 16 + q * 4;
            Us[kk+0][row] = ur[q].x; Us[kk+1][row] = ur[q].y;
            Us[kk+2][row] = ur[q].z; Us[kk+3][row] = ur[q].w;
            Vs[kk+0][row] = vr[q].x; Vs[kk+1][row] = vr[q].y;
            Vs[kk+2][row] = vr[q].z; Vs[kk+3][row] = vr[q].w;
        }
        __syncthreads();

        #pragma unroll 16
        for (int k = 0; k < 64; k++) {
            float4 u4 = *(const float4*)&Us[k][tx * 4];
            float4 v4 = *(const float4*)&Vs[k][ty * 4];
            float uu[4] = {u4.x, u4.y, u4.z, u4.w};
            float vv[4] = {v4.x, v4.y, v4.z, v4.w};
            #pragma unroll
            for (int r = 0; r < 4; r++)
                #pragma unroll
                for (int c = 0; c < 4; c++)
                    acc[r][c] += vv[r] * uu[c];
        }
    }

    float raL[4], rbL[4];
    #pragma unroll
    for (int c = 0; c < 4; c++) raL[c] = g_ra[b * P + i0 + tx * 4 + c];
    #pragma unroll
    for (int r = 0; r < 4; r++) rbL[r] = g_rb[b * P + j0 + ty * 4 + r];

    float qs = 0.f, q1 = 0.f;
    #pragma unroll
    for (int r = 0; r < 4; r++) {
        float4 o;
        o.x = 0.5f * (raL[0] + rbL[r]) - acc[r][0];
        o.y = 0.5f * (raL[1] + rbL[r]) - acc[r][1];
        o.z = 0.5f * (raL[2] + rbL[r]) - acc[r][2];
        o.w = 0.5f * (raL[3] + rbL[r]) - acc[r][3];
        qs += o.x*o.x + o.y*o.y + o.z*o.z + o.w*o.w;
        q1 += o.x + o.y + o.z + o.w;
        *(float4*)&g_qm[((size_t)b * P + j0 + ty * 4 + r) * P + i0 + tx * 4] = o;
    }
    qs = wred(qs);
    q1 = wred(q1);
    if ((tid & 31) == 0) { sQred[tid >> 5] = qs; sSred[tid >> 5] = q1; }
    __syncthreads();
    if (tid == 0) {
        float t = 0.f, t2 = 0.f;
        #pragma unroll
        for (int w = 0; w < 8; w++) { t += sQred[w]; t2 += sSred[w]; }
        atomicAdd(&g_qsq[b], t);
        atomicAdd(&g_qsum[b], t2);
    }
}

// ---------------- kernel 3: persistent QP solve, packed f32x2 math ------------
// 128 plain CTAs (8 per batch), each owns 64 rows of X in SMEM. Cross-CTA data
// goes through L2 (.cg) with a release/acquire counter barrier; every CTA
// redundantly computes all 512 column scales + scalar s — one barrier/iter.
#define SM_X      0                      // 32768 floats
#define SM_TW     32768                  // 16*512 per-warp T partials
#define SM_CW     (SM_TW + 8192)         // 16*512 per-warp colsum partials
#define SM_SCALE  (SM_CW + 8192)         // 512 (col scale, lazy)
#define SM_RED    (SM_SCALE + 512)       // 16
#define SM_S      (SM_RED + 16)          // 4
#define QP_SMEM_FLOATS (SM_S + 4)
#define QP_SMEM_BYTES  (QP_SMEM_FLOATS * 4)

__global__ void __launch_bounds__(512, 1)
qp_kernel(float* __restrict__ out) {
    extern __shared__ float sm[];
    float4*     sX4    = (float4*)(sm + SM_X);
    ulonglong2* sX2    = (ulonglong2*)(sm + SM_X);
    ulonglong2* sTw2   = (ulonglong2*)(sm + SM_TW);
    ulonglong2* sCw2   = (ulonglong2*)(sm + SM_CW);
    float*      sScale = sm + SM_SCALE;
    float4*     sSc4   = (float4*)sScale;
    ulonglong2* sSc2   = (ulonglong2*)sScale;
    float*      sRed   = sm + SM_RED;
    float*      sS     = sm + SM_S;

    const int b    = blockIdx.x >> 3;
    const int rank = blockIdx.x & 7;
    const int tid  = threadIdx.x;
    const int w    = tid >> 5, l = tid & 31;

    const float lr = 0.5f / (g_qsq[b] + 1e-8f);
    float s = g_qsum[b] * (1.f / 512.f);     // s0: X = 1/512, scale = 1
    const ulonglong2* qm2 = (const ulonglong2*)(g_qm + ((size_t)b * P + rank * 64) * P);

    // init: X = 1/512, scale = 1
    const float4 iv = make_float4(1.f/512, 1.f/512, 1.f/512, 1.f/512);
    for (int idx = tid; idx < 8192; idx += 512) sX4[idx] = iv;
    if (tid < 128) sSc4[tid] = make_float4(1.f, 1.f, 1.f, 1.f);
    __syncthreads();

    for (int it = 0; it < ITERS; it++) {
        const float cq = 2.f * lr * s;
        const ull ncq2 = pk2(-cq, -cq);

        // ---- phase A: gradient + clip + row-normalize + per-column T/C partials
        //      (single qm read per iteration; elementwise math packed f32x2)
        ull tA[8] = {}, cA[8] = {};          // [t][half]
        #pragma unroll
        for (int q = 0; q < 4; q++) {
            const int jl = w * 4 + q;
            const ulonglong2* qrow = qm2 + jl * 128;
            ulonglong2* xrow = sX2 + jl * 128;
            ulonglong2 qv[4];
            ull vv[8];
            ull rs2 = 0ull;
            #pragma unroll
            for (int t = 0; t < 4; t++) {
                const int c4 = l + 32 * t;
                qv[t] = qrow[c4];                          // LDG.128 (L2)
                ulonglong2 x2 = xrow[c4];                  // LDS.128
                ulonglong2 sc = sSc2[c4];                  // LDS.128
                ull v0 = fma2(ncq2, qv[t].x, mul2(x2.x, sc.x));
                ull v1 = fma2(ncq2, qv[t].y, mul2(x2.y, sc.y));
                v0 = clamp01_2(v0);                        // clip [0,1]
                v1 = clamp01_2(v1);
                vv[t * 2]     = v0;
                vv[t * 2 + 1] = v1;
                rs2 = add2(rs2, add2(v0, v1));
            }
            float rs = wred(hsum2(rs2));
            const float inv = 1.f / (rs + 1e-8f);
            const ull inv2 = pk2(inv, inv);
            #pragma unroll
            for (int t = 0; t < 4; t++) {
                const int c4 = l + 32 * t;
                ull v0 = mul2(vv[t * 2],     inv2);
                ull v1 = mul2(vv[t * 2 + 1], inv2);
                xrow[c4] = make_ulonglong2(v0, v1);        // STS.128 Xnorm
                tA[t * 2]     = fma2(qv[t].x, v0, tA[t * 2]);
                tA[t * 2 + 1] = fma2(qv[t].y, v1, tA[t * 2 + 1]);
                cA[t * 2]     = add2(cA[t * 2],     v0);
                cA[t * 2 + 1] = add2(cA[t * 2 + 1], v1);
            }
        }
        #pragma unroll
        for (int t = 0; t < 4; t++) {
            const int c4 = l + 32 * t;
            sTw2[w * 128 + c4] = make_ulonglong2(tA[t * 2], tA[t * 2 + 1]);
            sCw2[w * 128 + c4] = make_ulonglong2(cA[t * 2], cA[t * 2 + 1]);
        }
        __syncthreads();

        // ---- CTA-level column totals -> global partial slot (L2, .cg), packed
        const int buf = it & 1;
        float* gslot = g_part + ((size_t)buf * B + b) * 8192 + rank * 1024;
        if (tid < 256) {
            const int arr = tid >> 7;         // 0 -> T, 1 -> C
            const int c4  = tid & 127;
            const ulonglong2* src = (arr ? sCw2 : sTw2) + c4;
            ull a0 = 0ull, a1 = 0ull;
            #pragma unroll
            for (int ww = 0; ww < 16; ww++) {
                ulonglong2 vv2 = src[ww * 128];
                a0 = add2(a0, vv2.x);
                a1 = add2(a1, vv2.y);
            }
            float4 o;
            asm("mov.b64 {%0, %1}, %2;" : "=f"(o.x), "=f"(o.y) : "l"(a0));
            asm("mov.b64 {%0, %1}, %2;" : "=f"(o.z), "=f"(o.w) : "l"(a1));
            __stcg((float4*)(gslot + arr * 512) + c4, o);
        }
        __syncthreads();

        // ---- single global barrier per batch (release arrive, acquire spin)
        if (tid == 0) {
            asm volatile("red.release.gpu.global.add.u32 [%0], %1;"
                         :: "l"(&g_qpbar[b]), "r"(1u) : "memory");
            const unsigned target = 8u * (unsigned)(it + 1);
            unsigned v;
            do {
                asm volatile("ld.acquire.gpu.global.u32 %0, [%1];"
                             : "=r"(v) : "l"(&g_qpbar[b]) : "memory");
                if (v >= target) break;
                __nanosleep(32);
            } while (true);
        }
        __syncthreads();

        // ---- phase B (redundant per CTA): col scale for ALL 512 cols + scalar s
        {
            const float* pb = g_part + ((size_t)buf * B + b) * 8192;
            float Tt = 0.f, Ct = 0.f;
            #pragma unroll
            for (int r = 0; r < 8; r++) {
                Tt += __ldcg(pb + r * 1024 + tid);
                Ct += __ldcg(pb + r * 1024 + 512 + tid);
            }
            const float scl = fminf(1.f, 2.f / (Ct + 1e-8f));
            sScale[tid] = scl;
            float contrib = wred(scl * Tt);
            if (l == 0) sRed[w] = contrib;
        }
        __syncthreads();
        if (tid < 32) {
            float v = (tid < 16) ? sRed[tid] : 0.f;
            v = wred(v);
            if (tid == 0) sS[0] = v;
        }
        __syncthreads();
        s = sS[0];
    }

    // ---- writeout: apply final lazy col scale
    float4* out4 = (float4*)out + ((size_t)b * P + rank * 64) * 128;
    for (int idx = tid; idx < 8192; idx += 512) {
        float4 x = sX4[idx], sc = sSc4[idx & 127];
        out4[idx] = make_float4(x.x * sc.x, x.y * sc.y, x.z * sc.z, x.w * sc.w);
    }
}

// ---------------- launch -------------------------------------------------------
extern "C" void kernel_launch(void* const* d_in, const int* in_sizes, int n_in,
                              void* d_out, int out_size) {
    (void)in_sizes; (void)n_in; (void)out_size;
    const float* ncur = (const float*)d_in[0];
    const float* ecur = (const float*)d_in[1];
    const float* nnxt = (const float*)d_in[2];
    const float* enxt = (const float*)d_in[3];
    float* out = (float*)d_out;

    cudaFuncSetAttribute(qp_kernel, cudaFuncAttributeMaxDynamicSharedMemorySize, QP_SMEM_BYTES);

    norms_kernel<<<1024, 256>>>(ncur, ecur, nnxt, enxt);
    gram_kernel<<<dim3(8, 8, B), 256>>>(ncur, ecur, nnxt, enxt);
    qp_kernel<<<128, 512, QP_SMEM_BYTES>>>(out);
}